// round 6
// baseline (speedup 1.0000x reference)
#include <cuda_runtime.h>
#include <cuda_fp16.h>

#define N_USERS 100000
#define N_NODES 150000
#define E_MAX   4800000

// ---------------- static scratch (no allocation allowed) ----------------
__device__ int  d_counts[N_NODES];          // starts zeroed (.bss), self-zeroed in k_scan
__device__ int  d_rowptr[N_NODES + 1];
__device__ int  d_rank[E_MAX];              // intra-row rank of each edge
__device__ int2 d_perm[E_MAX];              // {col, val_bits} interleaved
__device__ __half2 d_x16[2][N_NODES * 32];  // ping-pong fp16 copy of current x slice

// ------- fused: layer-0 embedding write + histogram (rank-recording) -------
// blocks [0, GA): init out[:,0:64] + fp16 buf.  blocks [GA, ...): histogram.
#define GA 9375   // ceil(150000*16/256)

__global__ void k_init_hist(const float4* __restrict__ ue,
                            const float4* __restrict__ ie,
                            float4* __restrict__ out,
                            const int* __restrict__ rows, int e) {
    int b = blockIdx.x, t = threadIdx.x;
    if (b < GA) {
        int i = b * 256 + t;                 // over N_NODES*16
        if (i < N_NODES * 16) {
            int node = i >> 4, d4 = i & 15;
            float4 v = (node < N_USERS) ? ue[node * 16 + d4]
                                        : ie[(node - N_USERS) * 16 + d4];
            out[node * 64 + d4] = v;
            d_x16[0][node * 32 + 2 * d4]     = __floats2half2_rn(v.x, v.y);
            d_x16[0][node * 32 + 2 * d4 + 1] = __floats2half2_rn(v.z, v.w);
        }
    } else {
        int j = (b - GA) * 256 + t;
        if (j < e) {
            int r = __ldcs(&rows[j]);
            d_rank[j] = atomicAdd(&d_counts[r], 1);   // rank doubles as cursor
        }
    }
}

// ------- single-block exclusive scan of counts -> rowptr (int4, shfl-based) -------
__global__ __launch_bounds__(1024) void k_scan(int n) {
    __shared__ int wsum[32];
    __shared__ int carry_sh;
    int t = threadIdx.x, lane = t & 31, wid = t >> 5;
    if (t == 0) carry_sh = 0;
    __syncthreads();

    for (int base = 0; base < n; base += 4096) {
        int idx = base + t * 4;
        int4 c = make_int4(0, 0, 0, 0);
        if (idx + 3 < n) {
            c = *(int4*)&d_counts[idx];
            *(int4*)&d_counts[idx] = make_int4(0, 0, 0, 0);
        } else if (idx < n) {
            int* cp = &c.x;
            for (int j = 0; j < 4; ++j)
                if (idx + j < n) { cp[j] = d_counts[idx + j]; d_counts[idx + j] = 0; }
        }
        int tsum = c.x + c.y + c.z + c.w;

        int s = tsum;                                     // warp inclusive scan
        #pragma unroll
        for (int o = 1; o < 32; o <<= 1) {
            int x = __shfl_up_sync(0xffffffffu, s, o);
            if (lane >= o) s += x;
        }
        if (lane == 31) wsum[wid] = s;
        __syncthreads();
        if (wid == 0) {
            int ws = wsum[lane];
            #pragma unroll
            for (int o = 1; o < 32; o <<= 1) {
                int x = __shfl_up_sync(0xffffffffu, ws, o);
                if (lane >= o) ws += x;
            }
            wsum[lane] = ws;                              // inclusive warp sums
        }
        __syncthreads();
        int carry = carry_sh;
        int off = carry + (wid ? wsum[wid - 1] : 0) + (s - tsum);  // excl prefix
        int4 r;
        r.x = off; r.y = r.x + c.x; r.z = r.y + c.y; r.w = r.z + c.z;
        if (idx + 3 < n) {
            *(int4*)&d_rowptr[idx] = r;
        } else if (idx < n) {
            int* rp = &r.x;
            for (int j = 0; j < 4; ++j)
                if (idx + j < n) d_rowptr[idx + j] = rp[j];
        }
        __syncthreads();
        if (t == 1023) carry_sh = carry + wsum[31];       // add tile total
        __syncthreads();
    }
    if (t == 0) d_rowptr[n] = carry_sh;
}

// ---------------- scatter: atomic-free (rank precomputed) ----------------
__global__ void k_scatter(const int* __restrict__ rows,
                          const int* __restrict__ cols,
                          const float* __restrict__ vals, int e) {
    int i = blockIdx.x * blockDim.x + threadIdx.x;
    if (i < e) {
        int r = __ldcs(&rows[i]);
        int p = __ldg(&d_rowptr[r]) + __ldcs(&d_rank[i]);
        d_perm[p] = make_int2(__ldcs(&cols[i]), __float_as_int(__ldcs(&vals[i])));
    }
}

// ---------------- packed fp32x2 helpers (Blackwell) ----------------
__device__ __forceinline__ unsigned long long pack2(float a, float b) {
    unsigned long long r;
    asm("mov.b64 %0,{%1,%2};" : "=l"(r) : "f"(a), "f"(b));
    return r;
}
__device__ __forceinline__ void unpack2(unsigned long long v, float& a, float& b) {
    asm("mov.b64 {%0,%1},%2;" : "=f"(a), "=f"(b) : "l"(v));
}
__device__ __forceinline__ void ffma2(unsigned long long& acc, float s, float2 w) {
    asm("{\n\t"
        ".reg .b64 sa, wb;\n\t"
        "mov.b64 sa,{%1,%1};\n\t"
        "mov.b64 wb,{%2,%3};\n\t"
        "fma.rn.f32x2 %0, sa, wb, %0;\n\t"
        "}"
        : "+l"(acc) : "f"(s), "f"(w.x), "f"(w.y));
}

// ---------------- fused layer: SpMM + dense + leaky + L2-norm ----------------
// launch_bounds(256,4) -> 64 regs: no forced spills in the unrolled gather loop.
__global__ __launch_bounds__(256, 4) void k_layer(
    const float* __restrict__ W1, const float* __restrict__ b1,
    const float* __restrict__ W2, const float* __restrict__ b2,
    float* out, int k, int rows_per_block, int write16)
{
    __shared__ float Wsh[128 * 64];   // [i][j]: i<64 -> W1[k][j][i], i>=64 -> W2[k][j][i-64]
    __shared__ float bsh[64];
    __shared__ float ssh[8][128];     // per-warp staged [msg | interact]

    int t = threadIdx.x, lane = t & 31, wid = t >> 5;
    int src = k & 1, dst = src ^ 1;
    const __half2* __restrict__ xs = d_x16[src];

    const float* W1k = W1 + k * 4096;
    const float* W2k = W2 + k * 4096;
    for (int idx = t; idx < 128 * 64; idx += 256) {
        int i = idx >> 6, j = idx & 63;
        Wsh[idx] = (i < 64) ? W1k[j * 64 + i] : W2k[j * 64 + (i - 64)];
    }
    if (t < 64) bsh[t] = b1[k * 64 + t] + b2[k * 64 + t];
    __syncthreads();

    const int koff = k * 64;
    int r0 = blockIdx.x * rows_per_block;
    int r1 = min(r0 + rows_per_block, N_NODES);

    for (int r = r0 + wid; r < r1; r += 8) {
        // ---- SpMM: warp gathers this row's message (half2 per lane) ----
        int start = __ldg(&d_rowptr[r]);
        int stop  = __ldg(&d_rowptr[r + 1]);
        float a0 = 0.f, a1 = 0.f;
        #pragma unroll 8
        for (int e = start; e < stop; ++e) {
            int2 cv = __ldcs(&d_perm[e]);                // uniform across warp, streaming
            float v = __int_as_float(cv.y);
            __half2 h = __ldcg(&xs[(size_t)cv.x * 32 + lane]);
            float2 xv = __half22float2(h);
            a0 += v * xv.x;
            a1 += v * xv.y;
        }
        float2 xr = *(const float2*)(out + (size_t)r * 256 + koff + 2 * lane);

        // ---- stage s = [msg | msg*x] into shared ----
        __syncwarp();
        float* s = ssh[wid];
        s[2 * lane]          = a0;
        s[2 * lane + 1]      = a1;
        s[64 + 2 * lane]     = a0 * xr.x;
        s[64 + 2 * lane + 1] = a1 * xr.y;
        __syncwarp();

        // ---- dense: lane computes outputs j = 2*lane, 2*lane+1 ----
        unsigned long long acc = pack2(bsh[2 * lane], bsh[2 * lane + 1]);
        const float2* Wp = (const float2*)Wsh + lane;   // row i at Wp[i*32]
        #pragma unroll
        for (int i = 0; i < 128; i += 4) {
            float4 s4 = *(const float4*)&s[i];          // broadcast LDS.128
            ffma2(acc, s4.x, Wp[(i + 0) * 32]);
            ffma2(acc, s4.y, Wp[(i + 1) * 32]);
            ffma2(acc, s4.z, Wp[(i + 2) * 32]);
            ffma2(acc, s4.w, Wp[(i + 3) * 32]);
        }
        float h0, h1;
        unpack2(acc, h0, h1);
        h0 = h0 > 0.f ? h0 : 0.2f * h0;                 // leaky_relu(0.2)
        h1 = h1 > 0.f ? h1 : 0.2f * h1;

        float sq = h0 * h0 + h1 * h1;
        #pragma unroll
        for (int m = 16; m; m >>= 1) sq += __shfl_xor_sync(0xffffffffu, sq, m);
        float nrm = sqrtf(sq);
        float inv = 1.0f / fmaxf(nrm, 1e-12f);
        float o0 = h0 * inv, o1 = h1 * inv;

        *(float2*)(out + (size_t)r * 256 + koff + 64 + 2 * lane) = make_float2(o0, o1);
        if (write16)
            d_x16[dst][(size_t)r * 32 + lane] = __floats2half2_rn(o0, o1);
    }
}

// ---------------- launch ----------------
extern "C" void kernel_launch(void* const* d_in, const int* in_sizes, int n_in,
                              void* d_out, int out_size) {
    const float* ue   = (const float*)d_in[0];
    const float* ie   = (const float*)d_in[1];
    const float* W1   = (const float*)d_in[2];
    const float* b1   = (const float*)d_in[3];
    const float* W2   = (const float*)d_in[4];
    const float* b2   = (const float*)d_in[5];
    const float* vals = (const float*)d_in[6];
    const int*   rows = (const int*)d_in[7];
    const int*   cols = (const int*)d_in[8];
    float* out = (float*)d_out;
    int e = in_sizes[6];
    int L = in_sizes[2] / (64 * 64);

    // 0) layer-0 embeddings + histogram w/ rank recording
    int GB = (e + 255) / 256;
    k_init_hist<<<GA + GB, 256>>>((const float4*)ue, (const float4*)ie,
                                  (float4*)out, rows, e);
    // 1) rowptr scan (counts self-zeroed)
    k_scan<<<1, 1024>>>(N_NODES);
    // 2) atomic-free scatter
    k_scatter<<<(e + 255) / 256, 256>>>(rows, cols, vals, e);

    // 3-5) fused layers — 592 blocks = 4/SM on 148 SMs = one wave, spill-free regs
    const int DG = 592;
    const int rpb = (N_NODES + DG - 1) / DG;             // 254
    for (int k = 0; k < L; ++k)
        k_layer<<<DG, 256>>>(W1, b1, W2, b2, out, k, rpb, (k + 1 < L) ? 1 : 0);
}

// round 7
// speedup vs baseline: 1.0198x; 1.0198x over previous
#include <cuda_runtime.h>
#include <cuda_fp16.h>

#define N_USERS 100000
#define N_NODES 150000
#define E_MAX   4800000

// ---------------- static scratch (no allocation allowed) ----------------
__device__ int  d_counts[N_NODES];          // starts zeroed (.bss), self-zeroed in k_scan
__device__ int  d_rowptr[N_NODES + 1];
__device__ int  d_rank[E_MAX];              // intra-row rank of each edge
__device__ int2 d_perm[E_MAX];              // {col, val_bits} interleaved
__device__ __half2 d_x16[2][N_NODES * 32];  // ping-pong fp16 copy of current x slice

// ------- fused: layer-0 embedding write + histogram (rank-recording) -------
// blocks [0, GA): init out[:,0:64] + fp16 buf.  blocks [GA, ...): histogram.
#define GA 9375   // ceil(150000*16/256)

__global__ void k_init_hist(const float4* __restrict__ ue,
                            const float4* __restrict__ ie,
                            float4* __restrict__ out,
                            const int* __restrict__ rows, int e) {
    int b = blockIdx.x, t = threadIdx.x;
    if (b < GA) {
        int i = b * 256 + t;                 // over N_NODES*16
        if (i < N_NODES * 16) {
            int node = i >> 4, d4 = i & 15;
            float4 v = (node < N_USERS) ? ue[node * 16 + d4]
                                        : ie[(node - N_USERS) * 16 + d4];
            out[node * 64 + d4] = v;
            d_x16[0][node * 32 + 2 * d4]     = __floats2half2_rn(v.x, v.y);
            d_x16[0][node * 32 + 2 * d4 + 1] = __floats2half2_rn(v.z, v.w);
        }
    } else {
        int j = (b - GA) * 256 + t;
        if (j < e) {
            int r = __ldcs(&rows[j]);
            d_rank[j] = atomicAdd(&d_counts[r], 1);   // rank doubles as cursor
        }
    }
}

// ------- single-block exclusive scan of counts -> rowptr (int4, shfl-based) -------
__global__ __launch_bounds__(1024) void k_scan(int n) {
    __shared__ int wsum[32];
    __shared__ int carry_sh;
    int t = threadIdx.x, lane = t & 31, wid = t >> 5;
    if (t == 0) carry_sh = 0;
    __syncthreads();

    for (int base = 0; base < n; base += 4096) {
        int idx = base + t * 4;
        int4 c = make_int4(0, 0, 0, 0);
        if (idx + 3 < n) {
            c = *(int4*)&d_counts[idx];
            *(int4*)&d_counts[idx] = make_int4(0, 0, 0, 0);
        } else if (idx < n) {
            int* cp = &c.x;
            for (int j = 0; j < 4; ++j)
                if (idx + j < n) { cp[j] = d_counts[idx + j]; d_counts[idx + j] = 0; }
        }
        int tsum = c.x + c.y + c.z + c.w;

        int s = tsum;                                     // warp inclusive scan
        #pragma unroll
        for (int o = 1; o < 32; o <<= 1) {
            int x = __shfl_up_sync(0xffffffffu, s, o);
            if (lane >= o) s += x;
        }
        if (lane == 31) wsum[wid] = s;
        __syncthreads();
        if (wid == 0) {
            int ws = wsum[lane];
            #pragma unroll
            for (int o = 1; o < 32; o <<= 1) {
                int x = __shfl_up_sync(0xffffffffu, ws, o);
                if (lane >= o) ws += x;
            }
            wsum[lane] = ws;                              // inclusive warp sums
        }
        __syncthreads();
        int carry = carry_sh;
        int off = carry + (wid ? wsum[wid - 1] : 0) + (s - tsum);  // excl prefix
        int4 r;
        r.x = off; r.y = r.x + c.x; r.z = r.y + c.y; r.w = r.z + c.z;
        if (idx + 3 < n) {
            *(int4*)&d_rowptr[idx] = r;
        } else if (idx < n) {
            int* rp = &r.x;
            for (int j = 0; j < 4; ++j)
                if (idx + j < n) d_rowptr[idx + j] = rp[j];
        }
        __syncthreads();
        if (t == 1023) carry_sh = carry + wsum[31];       // add tile total
        __syncthreads();
    }
    if (t == 0) d_rowptr[n] = carry_sh;
}

// ---------------- scatter: atomic-free (rank precomputed) ----------------
__global__ void k_scatter(const int* __restrict__ rows,
                          const int* __restrict__ cols,
                          const float* __restrict__ vals, int e) {
    int i = blockIdx.x * blockDim.x + threadIdx.x;
    if (i < e) {
        int r = __ldcs(&rows[i]);
        int p = __ldg(&d_rowptr[r]) + __ldcs(&d_rank[i]);
        d_perm[p] = make_int2(__ldcs(&cols[i]), __float_as_int(__ldcs(&vals[i])));
    }
}

// ---------------- packed fp32x2 helpers (Blackwell) ----------------
__device__ __forceinline__ unsigned long long pack2(float a, float b) {
    unsigned long long r;
    asm("mov.b64 %0,{%1,%2};" : "=l"(r) : "f"(a), "f"(b));
    return r;
}
__device__ __forceinline__ void unpack2(unsigned long long v, float& a, float& b) {
    asm("mov.b64 {%0,%1},%2;" : "=f"(a), "=f"(b) : "l"(v));
}
__device__ __forceinline__ void ffma2(unsigned long long& acc, float s, float2 w) {
    asm("{\n\t"
        ".reg .b64 sa, wb;\n\t"
        "mov.b64 sa,{%1,%1};\n\t"
        "mov.b64 wb,{%2,%3};\n\t"
        "fma.rn.f32x2 %0, sa, wb, %0;\n\t"
        "}"
        : "+l"(acc) : "f"(s), "f"(w.x), "f"(w.y));
}

// ---------------- fused layer: SpMM + dense + leaky + L2-norm ----------------
// fp16 W in smem halves the crossbar traffic of the dense matvec (the L1tex
// binder per R6 profile). Paired-edge gather halves gather wavefronts+issue.
__global__ __launch_bounds__(256, 4) void k_layer(
    const float* __restrict__ W1, const float* __restrict__ b1,
    const float* __restrict__ W2, const float* __restrict__ b2,
    float* out, int k, int rows_per_block, int write16)
{
    __shared__ __half2 Wsh[128 * 32];  // [i][l] = half2(Wt[i][2l], Wt[i][2l+1])
    __shared__ float bsh[64];
    __shared__ float ssh[8][128];      // per-warp staged [msg | interact]

    int t = threadIdx.x, lane = t & 31, wid = t >> 5;
    int half = lane >> 4;              // which edge of the pair this lane serves
    int m = lane & 15;                 // dim group: dims 4m..4m+3
    int src = k & 1, dst = src ^ 1;
    const __half2* __restrict__ xs = d_x16[src];
    const int2* __restrict__ pm = d_perm;

    const float* W1k = W1 + k * 4096;
    const float* W2k = W2 + k * 4096;
    // Wt[i][j] = (i<64) ? W1[k][j][i] : W2[k][j][i-64]
    for (int idx = t; idx < 128 * 32; idx += 256) {
        int i = idx >> 5, l = idx & 31;
        float w0, w1;
        if (i < 64) { w0 = W1k[(2 * l) * 64 + i];     w1 = W1k[(2 * l + 1) * 64 + i]; }
        else        { w0 = W2k[(2 * l) * 64 + i - 64]; w1 = W2k[(2 * l + 1) * 64 + i - 64]; }
        Wsh[idx] = __floats2half2_rn(w0, w1);
    }
    if (t < 64) bsh[t] = b1[k * 64 + t] + b2[k * 64 + t];
    __syncthreads();

    const int koff = k * 64;
    int r0 = blockIdx.x * rows_per_block;
    int r1 = min(r0 + rows_per_block, N_NODES);

    for (int r = r0 + wid; r < r1; r += 8) {
        // ---- SpMM: 2 edges per iteration, half-warp each, 4 dims per lane ----
        int start = __ldg(&d_rowptr[r]);
        int len   = __ldg(&d_rowptr[r + 1]) - start;
        unsigned long long acc01 = 0ull, acc23 = 0ull;
        #pragma unroll 2
        for (int e = 0; e < len; e += 2) {
            int ee = e + half;
            int2 cv = __ldcs(&pm[start + min(ee, len - 1)]);
            float v = (ee < len) ? __int_as_float(cv.y) : 0.f;
            uint2 hx = __ldcg((const uint2*)(xs + (size_t)cv.x * 32) + m);
            float2 x01 = __half22float2(*(__half2*)&hx.x);
            float2 x23 = __half22float2(*(__half2*)&hx.y);
            ffma2(acc01, v, x01);
            ffma2(acc23, v, x23);
        }
        float a0, a1, a2, a3;
        unpack2(acc01, a0, a1);
        unpack2(acc23, a2, a3);
        a0 += __shfl_xor_sync(0xffffffffu, a0, 16);
        a1 += __shfl_xor_sync(0xffffffffu, a1, 16);
        a2 += __shfl_xor_sync(0xffffffffu, a2, 16);
        a3 += __shfl_xor_sync(0xffffffffu, a3, 16);

        // ---- stage s = [msg | msg*x] into shared (half-warp 0 writes) ----
        float* s = ssh[wid];
        if (half == 0) {
            float4 xr = *(const float4*)(out + (size_t)r * 256 + koff + 4 * m);
            *(float4*)&s[4 * m]      = make_float4(a0, a1, a2, a3);
            *(float4*)&s[64 + 4 * m] = make_float4(a0 * xr.x, a1 * xr.y,
                                                   a2 * xr.z, a3 * xr.w);
        }
        __syncwarp();

        // ---- dense: lane computes outputs j = 2*lane, 2*lane+1 ----
        unsigned long long acc = pack2(bsh[2 * lane], bsh[2 * lane + 1]);
        const __half2* Wp = Wsh + lane;                 // row i at Wp[i*32]
        #pragma unroll
        for (int i = 0; i < 128; i += 4) {
            float4 s4 = *(const float4*)&s[i];          // broadcast LDS.128
            float2 w0 = __half22float2(Wp[(i + 0) * 32]);
            float2 w1 = __half22float2(Wp[(i + 1) * 32]);
            float2 w2 = __half22float2(Wp[(i + 2) * 32]);
            float2 w3 = __half22float2(Wp[(i + 3) * 32]);
            ffma2(acc, s4.x, w0);
            ffma2(acc, s4.y, w1);
            ffma2(acc, s4.z, w2);
            ffma2(acc, s4.w, w3);
        }
        float h0, h1;
        unpack2(acc, h0, h1);
        h0 = h0 > 0.f ? h0 : 0.2f * h0;                 // leaky_relu(0.2)
        h1 = h1 > 0.f ? h1 : 0.2f * h1;

        float sq = h0 * h0 + h1 * h1;
        #pragma unroll
        for (int mm = 16; mm; mm >>= 1) sq += __shfl_xor_sync(0xffffffffu, sq, mm);
        float nrm = sqrtf(sq);
        float inv = 1.0f / fmaxf(nrm, 1e-12f);
        float o0 = h0 * inv, o1 = h1 * inv;

        *(float2*)(out + (size_t)r * 256 + koff + 64 + 2 * lane) = make_float2(o0, o1);
        if (write16)
            d_x16[dst][(size_t)r * 32 + lane] = __floats2half2_rn(o0, o1);
        __syncwarp();
    }
}

// ---------------- launch ----------------
extern "C" void kernel_launch(void* const* d_in, const int* in_sizes, int n_in,
                              void* d_out, int out_size) {
    const float* ue   = (const float*)d_in[0];
    const float* ie   = (const float*)d_in[1];
    const float* W1   = (const float*)d_in[2];
    const float* b1   = (const float*)d_in[3];
    const float* W2   = (const float*)d_in[4];
    const float* b2   = (const float*)d_in[5];
    const float* vals = (const float*)d_in[6];
    const int*   rows = (const int*)d_in[7];
    const int*   cols = (const int*)d_in[8];
    float* out = (float*)d_out;
    int e = in_sizes[6];
    int L = in_sizes[2] / (64 * 64);

    // 0) layer-0 embeddings + histogram w/ rank recording
    int GB = (e + 255) / 256;
    k_init_hist<<<GA + GB, 256>>>((const float4*)ue, (const float4*)ie,
                                  (float4*)out, rows, e);
    // 1) rowptr scan (counts self-zeroed)
    k_scan<<<1, 1024>>>(N_NODES);
    // 2) atomic-free scatter
    k_scatter<<<(e + 255) / 256, 256>>>(rows, cols, vals, e);

    // 3-5) fused layers — 592 blocks = 4/SM on 148 SMs = one wave
    const int DG = 592;
    const int rpb = (N_NODES + DG - 1) / DG;             // 254
    for (int k = 0; k < L; ++k)
        k_layer<<<DG, 256>>>(W1, b1, W2, b2, out, k, rpb, (k + 1 < L) ? 1 : 0);
}

// round 10
// speedup vs baseline: 1.0605x; 1.0399x over previous
#include <cuda_runtime.h>
#include <cuda_fp16.h>

#define N_USERS 100000
#define N_NODES 150000
#define E_MAX   4800000

// ---------------- static scratch (no allocation allowed) ----------------
__device__ int  d_counts[N_NODES];          // starts zeroed (.bss), self-zeroed in k_scan
__device__ int  d_rowptr[N_NODES + 1];
__device__ int  d_rank[E_MAX];              // intra-row rank of each edge
__device__ int2 d_perm[E_MAX];              // {col, val_bits} interleaved
__device__ __half2 d_x16[2][N_NODES * 32];  // ping-pong fp16 copy of current x slice

// ------- fused: layer-0 embedding write + histogram (rank-recording) -------
#define GA 9375   // ceil(150000*16/256)

__global__ void k_init_hist(const float4* __restrict__ ue,
                            const float4* __restrict__ ie,
                            float4* __restrict__ out,
                            const int* __restrict__ rows, int e) {
    int b = blockIdx.x, t = threadIdx.x;
    if (b < GA) {
        int i = b * 256 + t;                 // over N_NODES*16
        if (i < N_NODES * 16) {
            int node = i >> 4, d4 = i & 15;
            float4 v = (node < N_USERS) ? ue[node * 16 + d4]
                                        : ie[(node - N_USERS) * 16 + d4];
            out[node * 64 + d4] = v;
            d_x16[0][node * 32 + 2 * d4]     = __floats2half2_rn(v.x, v.y);
            d_x16[0][node * 32 + 2 * d4 + 1] = __floats2half2_rn(v.z, v.w);
        }
    } else {
        int j = (b - GA) * 256 + t;
        if (j < e) {
            int r = __ldcs(&rows[j]);
            d_rank[j] = atomicAdd(&d_counts[r], 1);   // rank doubles as cursor
        }
    }
}

// ------- single-block exclusive scan of counts -> rowptr (int4, shfl-based) -------
__global__ __launch_bounds__(1024) void k_scan(int n) {
    __shared__ int wsum[32];
    __shared__ int carry_sh;
    int t = threadIdx.x, lane = t & 31, wid = t >> 5;
    if (t == 0) carry_sh = 0;
    __syncthreads();

    for (int base = 0; base < n; base += 4096) {
        int idx = base + t * 4;
        int4 c = make_int4(0, 0, 0, 0);
        if (idx + 3 < n) {
            c = *(int4*)&d_counts[idx];
            *(int4*)&d_counts[idx] = make_int4(0, 0, 0, 0);
        } else if (idx < n) {
            int* cp = &c.x;
            for (int j = 0; j < 4; ++j)
                if (idx + j < n) { cp[j] = d_counts[idx + j]; d_counts[idx + j] = 0; }
        }
        int tsum = c.x + c.y + c.z + c.w;

        int s = tsum;                                     // warp inclusive scan
        #pragma unroll
        for (int o = 1; o < 32; o <<= 1) {
            int x = __shfl_up_sync(0xffffffffu, s, o);
            if (lane >= o) s += x;
        }
        if (lane == 31) wsum[wid] = s;
        __syncthreads();
        if (wid == 0) {
            int ws = wsum[lane];
            #pragma unroll
            for (int o = 1; o < 32; o <<= 1) {
                int x = __shfl_up_sync(0xffffffffu, ws, o);
                if (lane >= o) ws += x;
            }
            wsum[lane] = ws;                              // inclusive warp sums
        }
        __syncthreads();
        int carry = carry_sh;
        int off = carry + (wid ? wsum[wid - 1] : 0) + (s - tsum);  // excl prefix
        int4 r;
        r.x = off; r.y = r.x + c.x; r.z = r.y + c.y; r.w = r.z + c.z;
        if (idx + 3 < n) {
            *(int4*)&d_rowptr[idx] = r;
        } else if (idx < n) {
            int* rp = &r.x;
            for (int j = 0; j < 4; ++j)
                if (idx + j < n) d_rowptr[idx + j] = rp[j];
        }
        __syncthreads();
        if (t == 1023) carry_sh = carry + wsum[31];       // add tile total
        __syncthreads();
    }
    if (t == 0) d_rowptr[n] = carry_sh;
}

// ---------------- scatter: atomic-free (rank precomputed) ----------------
__global__ void k_scatter(const int* __restrict__ rows,
                          const int* __restrict__ cols,
                          const float* __restrict__ vals, int e) {
    int i = blockIdx.x * blockDim.x + threadIdx.x;
    if (i < e) {
        int r = __ldcs(&rows[i]);
        int p = __ldg(&d_rowptr[r]) + __ldcs(&d_rank[i]);
        d_perm[p] = make_int2(__ldcs(&cols[i]), __float_as_int(__ldcs(&vals[i])));
    }
}

// ---------------- packed fp32x2 helpers (Blackwell) ----------------
__device__ __forceinline__ unsigned long long pack2(float a, float b) {
    unsigned long long r;
    asm("mov.b64 %0,{%1,%2};" : "=l"(r) : "f"(a), "f"(b));
    return r;
}
__device__ __forceinline__ void unpack2(unsigned long long v, float& a, float& b) {
    asm("mov.b64 {%0,%1},%2;" : "=f"(a), "=f"(b) : "l"(v));
}
__device__ __forceinline__ void ffma2(unsigned long long& acc, float s, float2 w) {
    asm("{\n\t"
        ".reg .b64 sa, wb;\n\t"
        "mov.b64 sa,{%1,%1};\n\t"
        "mov.b64 wb,{%2,%3};\n\t"
        "fma.rn.f32x2 %0, sa, wb, %0;\n\t"
        "}"
        : "+l"(acc) : "f"(s), "f"(w.x), "f"(w.y));
}

// ---------------- fused layer: SpMM + dense + leaky + L2-norm ----------------
// Gather-latency bound (R7 profile: issue 47%, L1 57%). Deep unroll (8) keeps
// ~8 independent gather loads in flight per warp; two packed accumulators
// split the FMA dependency chain. Dense uses fp16 W (halved crossbar bytes).
__global__ __launch_bounds__(256, 4) void k_layer(
    const float* __restrict__ W1, const float* __restrict__ b1,
    const float* __restrict__ W2, const float* __restrict__ b2,
    float* out, int k, int rows_per_block, int write16)
{
    __shared__ __half2 Wsh[128 * 32];  // [i][l] = half2(Wt[i][2l], Wt[i][2l+1])
    __shared__ float bsh[64];
    __shared__ float ssh[8][128];      // per-warp staged [msg | interact]

    int t = threadIdx.x, lane = t & 31, wid = t >> 5;
    int src = k & 1, dst = src ^ 1;
    const __half2* __restrict__ xs = d_x16[src];
    const int2* __restrict__ pm = d_perm;

    const float* W1k = W1 + k * 4096;
    const float* W2k = W2 + k * 4096;
    // Wt[i][j] = (i<64) ? W1[k][j][i] : W2[k][j][i-64]
    for (int idx = t; idx < 128 * 32; idx += 256) {
        int i = idx >> 5, l = idx & 31;
        float w0, w1;
        if (i < 64) { w0 = W1k[(2 * l) * 64 + i];      w1 = W1k[(2 * l + 1) * 64 + i]; }
        else        { w0 = W2k[(2 * l) * 64 + i - 64]; w1 = W2k[(2 * l + 1) * 64 + i - 64]; }
        Wsh[idx] = __floats2half2_rn(w0, w1);
    }
    if (t < 64) bsh[t] = b1[k * 64 + t] + b2[k * 64 + t];
    __syncthreads();

    const int koff = k * 64;
    int r0 = blockIdx.x * rows_per_block;
    int r1 = min(r0 + rows_per_block, N_NODES);

    for (int r = r0 + wid; r < r1; r += 8) {
        // ---- SpMM: warp per row, lane owns dims 2l,2l+1; unroll 8 for MLP ----
        int start = __ldg(&d_rowptr[r]);
        int stop  = __ldg(&d_rowptr[r + 1]);
        unsigned long long accA = 0ull, accB = 0ull;   // two chains
        int e = start;
        #pragma unroll 1
        for (; e + 8 <= stop; e += 8) {
            int2 cv0 = __ldcs(&pm[e + 0]);
            int2 cv1 = __ldcs(&pm[e + 1]);
            int2 cv2 = __ldcs(&pm[e + 2]);
            int2 cv3 = __ldcs(&pm[e + 3]);
            int2 cv4 = __ldcs(&pm[e + 4]);
            int2 cv5 = __ldcs(&pm[e + 5]);
            int2 cv6 = __ldcs(&pm[e + 6]);
            int2 cv7 = __ldcs(&pm[e + 7]);
            __half2 h0 = __ldcg(&xs[(size_t)cv0.x * 32 + lane]);
            __half2 h1 = __ldcg(&xs[(size_t)cv1.x * 32 + lane]);
            __half2 h2 = __ldcg(&xs[(size_t)cv2.x * 32 + lane]);
            __half2 h3 = __ldcg(&xs[(size_t)cv3.x * 32 + lane]);
            __half2 h4 = __ldcg(&xs[(size_t)cv4.x * 32 + lane]);
            __half2 h5 = __ldcg(&xs[(size_t)cv5.x * 32 + lane]);
            __half2 h6 = __ldcg(&xs[(size_t)cv6.x * 32 + lane]);
            __half2 h7 = __ldcg(&xs[(size_t)cv7.x * 32 + lane]);
            ffma2(accA, __int_as_float(cv0.y), __half22float2(h0));
            ffma2(accB, __int_as_float(cv1.y), __half22float2(h1));
            ffma2(accA, __int_as_float(cv2.y), __half22float2(h2));
            ffma2(accB, __int_as_float(cv3.y), __half22float2(h3));
            ffma2(accA, __int_as_float(cv4.y), __half22float2(h4));
            ffma2(accB, __int_as_float(cv5.y), __half22float2(h5));
            ffma2(accA, __int_as_float(cv6.y), __half22float2(h6));
            ffma2(accB, __int_as_float(cv7.y), __half22float2(h7));
        }
        #pragma unroll 1
        for (; e < stop; ++e) {
            int2 cv = __ldcs(&pm[e]);
            __half2 h = __ldcg(&xs[(size_t)cv.x * 32 + lane]);
            ffma2(accA, __int_as_float(cv.y), __half22float2(h));
        }
        float a0, a1, b0v, b1v;
        unpack2(accA, a0, a1);
        unpack2(accB, b0v, b1v);
        a0 += b0v;
        a1 += b1v;
        float2 xr = *(const float2*)(out + (size_t)r * 256 + koff + 2 * lane);

        // ---- stage s = [msg | msg*x] into shared ----
        __syncwarp();
        float* s = ssh[wid];
        s[2 * lane]          = a0;
        s[2 * lane + 1]      = a1;
        s[64 + 2 * lane]     = a0 * xr.x;
        s[64 + 2 * lane + 1] = a1 * xr.y;
        __syncwarp();

        // ---- dense: lane computes outputs j = 2*lane, 2*lane+1 ----
        unsigned long long acc = pack2(bsh[2 * lane], bsh[2 * lane + 1]);
        const __half2* Wp = Wsh + lane;                 // row i at Wp[i*32]
        #pragma unroll
        for (int i = 0; i < 128; i += 4) {
            float4 s4 = *(const float4*)&s[i];          // broadcast LDS.128
            float2 w0 = __half22float2(Wp[(i + 0) * 32]);
            float2 w1 = __half22float2(Wp[(i + 1) * 32]);
            float2 w2 = __half22float2(Wp[(i + 2) * 32]);
            float2 w3 = __half22float2(Wp[(i + 3) * 32]);
            ffma2(acc, s4.x, w0);
            ffma2(acc, s4.y, w1);
            ffma2(acc, s4.z, w2);
            ffma2(acc, s4.w, w3);
        }
        float h0, h1;
        unpack2(acc, h0, h1);
        h0 = h0 > 0.f ? h0 : 0.2f * h0;                 // leaky_relu(0.2)
        h1 = h1 > 0.f ? h1 : 0.2f * h1;

        float sq = h0 * h0 + h1 * h1;
        #pragma unroll
        for (int mm = 16; mm; mm >>= 1) sq += __shfl_xor_sync(0xffffffffu, sq, mm);
        float nrm = sqrtf(sq);
        float inv = 1.0f / fmaxf(nrm, 1e-12f);
        float o0 = h0 * inv, o1 = h1 * inv;

        *(float2*)(out + (size_t)r * 256 + koff + 64 + 2 * lane) = make_float2(o0, o1);
        if (write16)
            d_x16[dst][(size_t)r * 32 + lane] = __floats2half2_rn(o0, o1);
        __syncwarp();
    }
}

// ---------------- launch ----------------
extern "C" void kernel_launch(void* const* d_in, const int* in_sizes, int n_in,
                              void* d_out, int out_size) {
    const float* ue   = (const float*)d_in[0];
    const float* ie   = (const float*)d_in[1];
    const float* W1   = (const float*)d_in[2];
    const float* b1   = (const float*)d_in[3];
    const float* W2   = (const float*)d_in[4];
    const float* b2   = (const float*)d_in[5];
    const float* vals = (const float*)d_in[6];
    const int*   rows = (const int*)d_in[7];
    const int*   cols = (const int*)d_in[8];
    float* out = (float*)d_out;
    int e = in_sizes[6];
    int L = in_sizes[2] / (64 * 64);

    // 0) layer-0 embeddings + histogram w/ rank recording
    int GB = (e + 255) / 256;
    k_init_hist<<<GA + GB, 256>>>((const float4*)ue, (const float4*)ie,
                                  (float4*)out, rows, e);
    // 1) rowptr scan (counts self-zeroed)
    k_scan<<<1, 1024>>>(N_NODES);
    // 2) atomic-free scatter
    k_scatter<<<(e + 255) / 256, 256>>>(rows, cols, vals, e);

    // 3-5) fused layers — 592 blocks = 4/SM on 148 SMs = one wave
    const int DG = 592;
    const int rpb = (N_NODES + DG - 1) / DG;             // 254
    for (int k = 0; k < L; ++k)
        k_layer<<<DG, 256>>>(W1, b1, W2, b2, out, k, rpb, (k + 1 < L) ? 1 : 0);
}

// round 11
// speedup vs baseline: 1.2644x; 1.1922x over previous
#include <cuda_runtime.h>
#include <cuda_fp16.h>

#define N_USERS 100000
#define N_NODES 150000
#define E_MAX   4800000

// ---------------- static scratch (no allocation allowed) ----------------
__device__ int  d_counts[N_NODES];          // starts zeroed (.bss), self-zeroed in k_scan
__device__ int  d_rowptr[N_NODES + 1];
__device__ int  d_rank[E_MAX];              // intra-row rank of each edge
__device__ int2 d_perm[E_MAX];              // {col, val_bits} interleaved
__device__ __half2 d_x16[2][N_NODES * 32];  // ping-pong fp16 copy of current x slice

// ------- fused: layer-0 embedding write + histogram (rank-recording) -------
#define GA 9375   // ceil(150000*16/256)

__global__ void k_init_hist(const float4* __restrict__ ue,
                            const float4* __restrict__ ie,
                            float4* __restrict__ out,
                            const int* __restrict__ rows, int e) {
    int b = blockIdx.x, t = threadIdx.x;
    if (b < GA) {
        int i = b * 256 + t;                 // over N_NODES*16
        if (i < N_NODES * 16) {
            int node = i >> 4, d4 = i & 15;
            float4 v = (node < N_USERS) ? ue[node * 16 + d4]
                                        : ie[(node - N_USERS) * 16 + d4];
            out[node * 64 + d4] = v;
            d_x16[0][node * 32 + 2 * d4]     = __floats2half2_rn(v.x, v.y);
            d_x16[0][node * 32 + 2 * d4 + 1] = __floats2half2_rn(v.z, v.w);
        }
    } else {
        int j = (b - GA) * 256 + t;
        if (j < e) {
            int r = __ldcs(&rows[j]);
            d_rank[j] = atomicAdd(&d_counts[r], 1);   // rank doubles as cursor
        }
    }
}

// ------- single-block exclusive scan of counts -> rowptr (int4, shfl-based) -------
__global__ __launch_bounds__(1024) void k_scan(int n) {
    __shared__ int wsum[32];
    __shared__ int carry_sh;
    int t = threadIdx.x, lane = t & 31, wid = t >> 5;
    if (t == 0) carry_sh = 0;
    __syncthreads();

    for (int base = 0; base < n; base += 4096) {
        int idx = base + t * 4;
        int4 c = make_int4(0, 0, 0, 0);
        if (idx + 3 < n) {
            c = *(int4*)&d_counts[idx];
            *(int4*)&d_counts[idx] = make_int4(0, 0, 0, 0);
        } else if (idx < n) {
            int* cp = &c.x;
            for (int j = 0; j < 4; ++j)
                if (idx + j < n) { cp[j] = d_counts[idx + j]; d_counts[idx + j] = 0; }
        }
        int tsum = c.x + c.y + c.z + c.w;

        int s = tsum;                                     // warp inclusive scan
        #pragma unroll
        for (int o = 1; o < 32; o <<= 1) {
            int x = __shfl_up_sync(0xffffffffu, s, o);
            if (lane >= o) s += x;
        }
        if (lane == 31) wsum[wid] = s;
        __syncthreads();
        if (wid == 0) {
            int ws = wsum[lane];
            #pragma unroll
            for (int o = 1; o < 32; o <<= 1) {
                int x = __shfl_up_sync(0xffffffffu, ws, o);
                if (lane >= o) ws += x;
            }
            wsum[lane] = ws;                              // inclusive warp sums
        }
        __syncthreads();
        int carry = carry_sh;
        int off = carry + (wid ? wsum[wid - 1] : 0) + (s - tsum);  // excl prefix
        int4 r;
        r.x = off; r.y = r.x + c.x; r.z = r.y + c.y; r.w = r.z + c.z;
        if (idx + 3 < n) {
            *(int4*)&d_rowptr[idx] = r;
        } else if (idx < n) {
            int* rp = &r.x;
            for (int j = 0; j < 4; ++j)
                if (idx + j < n) d_rowptr[idx + j] = rp[j];
        }
        __syncthreads();
        if (t == 1023) carry_sh = carry + wsum[31];       // add tile total
        __syncthreads();
    }
    if (t == 0) d_rowptr[n] = carry_sh;
}

// ---------------- scatter: atomic-free (rank precomputed) ----------------
__global__ void k_scatter(const int* __restrict__ rows,
                          const int* __restrict__ cols,
                          const float* __restrict__ vals, int e) {
    int i = blockIdx.x * blockDim.x + threadIdx.x;
    if (i < e) {
        int r = __ldcs(&rows[i]);
        int p = __ldg(&d_rowptr[r]) + __ldcs(&d_rank[i]);
        d_perm[p] = make_int2(__ldcs(&cols[i]), __float_as_int(__ldcs(&vals[i])));
    }
}

// ---------------- packed fp32x2 helpers (Blackwell) ----------------
__device__ __forceinline__ unsigned long long pack2(float a, float b) {
    unsigned long long r;
    asm("mov.b64 %0,{%1,%2};" : "=l"(r) : "f"(a), "f"(b));
    return r;
}
__device__ __forceinline__ void unpack2(unsigned long long v, float& a, float& b) {
    asm("mov.b64 {%0,%1},%2;" : "=f"(a), "=f"(b) : "l"(v));
}
__device__ __forceinline__ void ffma2(unsigned long long& acc, float s, float2 w) {
    asm("{\n\t"
        ".reg .b64 sa, wb;\n\t"
        "mov.b64 sa,{%1,%1};\n\t"
        "mov.b64 wb,{%2,%3};\n\t"
        "fma.rn.f32x2 %0, sa, wb, %0;\n\t"
        "}"
        : "+l"(acc) : "f"(s), "f"(w.x), "f"(w.y));
}

// ------- fused layer: gather(4 rows/warp) + shared-W dense + leaky + L2-norm -------
// Instruction-bound (R10: issue 50%, ~820 instrs/row). Dense now batches 4 rows
// per W sweep with fp32 W (no converts): ~192 dense instrs/row vs ~544.
__global__ __launch_bounds__(256, 4) void k_layer(
    const float* __restrict__ W1, const float* __restrict__ b1,
    const float* __restrict__ W2, const float* __restrict__ b2,
    float* out, int k, int rows_per_block, int write16)
{
    __shared__ float2 Wsh[128 * 32];   // [i][l] = float2(Wt[i][2l], Wt[i][2l+1])
    __shared__ float bsh[64];
    __shared__ float ssh[8][4][128];   // per-warp, 4 rows of staged [msg | interact]

    int t = threadIdx.x, lane = t & 31, wid = t >> 5;
    int src = k & 1, dst = src ^ 1;
    const __half2* __restrict__ xs = d_x16[src];
    const int2* __restrict__ pm = d_perm;

    const float* W1k = W1 + k * 4096;
    const float* W2k = W2 + k * 4096;
    // Wt[i][j] = (i<64) ? W1[k][j][i] : W2[k][j][i-64]
    for (int idx = t; idx < 128 * 32; idx += 256) {
        int i = idx >> 5, l = idx & 31;
        float w0, w1;
        if (i < 64) { w0 = W1k[(2 * l) * 64 + i];      w1 = W1k[(2 * l + 1) * 64 + i]; }
        else        { w0 = W2k[(2 * l) * 64 + i - 64]; w1 = W2k[(2 * l + 1) * 64 + i - 64]; }
        Wsh[idx] = make_float2(w0, w1);
    }
    if (t < 64) bsh[t] = b1[k * 64 + t] + b2[k * 64 + t];
    __syncthreads();

    const int koff = k * 64;
    int r0 = blockIdx.x * rows_per_block;
    int r1 = min(r0 + rows_per_block, N_NODES);

    for (int gbase = r0 + wid * 4; gbase < r1; gbase += 32) {
        // ---- gather 4 rows (full warp per row, unroll-8 for MLP) ----
        #pragma unroll 1
        for (int rr = 0; rr < 4; ++rr) {
            int r = gbase + rr;
            int start = 0, stop = 0;
            if (r < r1) {
                start = __ldg(&d_rowptr[r]);
                stop  = __ldg(&d_rowptr[r + 1]);
            }
            unsigned long long accA = 0ull, accB = 0ull;
            int e = start;
            #pragma unroll 1
            for (; e + 8 <= stop; e += 8) {
                int2 cv0 = __ldcs(&pm[e + 0]);
                int2 cv1 = __ldcs(&pm[e + 1]);
                int2 cv2 = __ldcs(&pm[e + 2]);
                int2 cv3 = __ldcs(&pm[e + 3]);
                int2 cv4 = __ldcs(&pm[e + 4]);
                int2 cv5 = __ldcs(&pm[e + 5]);
                int2 cv6 = __ldcs(&pm[e + 6]);
                int2 cv7 = __ldcs(&pm[e + 7]);
                __half2 h0 = __ldcg(&xs[(size_t)cv0.x * 32 + lane]);
                __half2 h1 = __ldcg(&xs[(size_t)cv1.x * 32 + lane]);
                __half2 h2 = __ldcg(&xs[(size_t)cv2.x * 32 + lane]);
                __half2 h3 = __ldcg(&xs[(size_t)cv3.x * 32 + lane]);
                __half2 h4 = __ldcg(&xs[(size_t)cv4.x * 32 + lane]);
                __half2 h5 = __ldcg(&xs[(size_t)cv5.x * 32 + lane]);
                __half2 h6 = __ldcg(&xs[(size_t)cv6.x * 32 + lane]);
                __half2 h7 = __ldcg(&xs[(size_t)cv7.x * 32 + lane]);
                ffma2(accA, __int_as_float(cv0.y), __half22float2(h0));
                ffma2(accB, __int_as_float(cv1.y), __half22float2(h1));
                ffma2(accA, __int_as_float(cv2.y), __half22float2(h2));
                ffma2(accB, __int_as_float(cv3.y), __half22float2(h3));
                ffma2(accA, __int_as_float(cv4.y), __half22float2(h4));
                ffma2(accB, __int_as_float(cv5.y), __half22float2(h5));
                ffma2(accA, __int_as_float(cv6.y), __half22float2(h6));
                ffma2(accB, __int_as_float(cv7.y), __half22float2(h7));
            }
            #pragma unroll 1
            for (; e < stop; ++e) {
                int2 cv = __ldcs(&pm[e]);
                __half2 h = __ldcg(&xs[(size_t)cv.x * 32 + lane]);
                ffma2(accA, __int_as_float(cv.y), __half22float2(h));
            }
            float a0, a1, b0v, b1v;
            unpack2(accA, a0, a1);
            unpack2(accB, b0v, b1v);
            a0 += b0v;
            a1 += b1v;
            float2 xr = make_float2(0.f, 0.f);
            if (r < r1)
                xr = *(const float2*)(out + (size_t)r * 256 + koff + 2 * lane);
            float* s = ssh[wid][rr];
            s[2 * lane]          = a0;
            s[2 * lane + 1]      = a1;
            s[64 + 2 * lane]     = a0 * xr.x;
            s[64 + 2 * lane + 1] = a1 * xr.y;
        }
        __syncwarp();

        // ---- dense: 4 rows share each W read; lane owns outputs 2l, 2l+1 ----
        unsigned long long binit = pack2(bsh[2 * lane], bsh[2 * lane + 1]);
        unsigned long long acc0 = binit, acc1 = binit, acc2 = binit, acc3 = binit;
        const float2* Wp = Wsh + lane;                  // row i at Wp[i*32]
        const float (*sb)[128] = ssh[wid];
        #pragma unroll
        for (int i = 0; i < 128; i += 4) {
            float2 w0 = Wp[(i + 0) * 32];
            float2 w1 = Wp[(i + 1) * 32];
            float2 w2 = Wp[(i + 2) * 32];
            float2 w3 = Wp[(i + 3) * 32];
            float4 sA = *(const float4*)&sb[0][i];
            float4 sB = *(const float4*)&sb[1][i];
            float4 sC = *(const float4*)&sb[2][i];
            float4 sD = *(const float4*)&sb[3][i];
            ffma2(acc0, sA.x, w0); ffma2(acc0, sA.y, w1);
            ffma2(acc0, sA.z, w2); ffma2(acc0, sA.w, w3);
            ffma2(acc1, sB.x, w0); ffma2(acc1, sB.y, w1);
            ffma2(acc1, sB.z, w2); ffma2(acc1, sB.w, w3);
            ffma2(acc2, sC.x, w0); ffma2(acc2, sC.y, w1);
            ffma2(acc2, sC.z, w2); ffma2(acc2, sC.w, w3);
            ffma2(acc3, sD.x, w0); ffma2(acc3, sD.y, w1);
            ffma2(acc3, sD.z, w2); ffma2(acc3, sD.w, w3);
        }

        // ---- epilogue per row: leaky + warp L2-norm + writes ----
        unsigned long long accs[4] = {acc0, acc1, acc2, acc3};
        #pragma unroll
        for (int rr = 0; rr < 4; ++rr) {
            int r = gbase + rr;
            float h0, h1;
            unpack2(accs[rr], h0, h1);
            h0 = h0 > 0.f ? h0 : 0.2f * h0;             // leaky_relu(0.2)
            h1 = h1 > 0.f ? h1 : 0.2f * h1;
            float sq = h0 * h0 + h1 * h1;
            #pragma unroll
            for (int mm = 16; mm; mm >>= 1)
                sq += __shfl_xor_sync(0xffffffffu, sq, mm);
            float inv = 1.0f / fmaxf(sqrtf(sq), 1e-12f);
            float o0 = h0 * inv, o1 = h1 * inv;
            if (r < r1) {
                *(float2*)(out + (size_t)r * 256 + koff + 64 + 2 * lane) =
                    make_float2(o0, o1);
                if (write16)
                    d_x16[dst][(size_t)r * 32 + lane] = __floats2half2_rn(o0, o1);
            }
        }
        __syncwarp();
    }
}

// ---------------- launch ----------------
extern "C" void kernel_launch(void* const* d_in, const int* in_sizes, int n_in,
                              void* d_out, int out_size) {
    const float* ue   = (const float*)d_in[0];
    const float* ie   = (const float*)d_in[1];
    const float* W1   = (const float*)d_in[2];
    const float* b1   = (const float*)d_in[3];
    const float* W2   = (const float*)d_in[4];
    const float* b2   = (const float*)d_in[5];
    const float* vals = (const float*)d_in[6];
    const int*   rows = (const int*)d_in[7];
    const int*   cols = (const int*)d_in[8];
    float* out = (float*)d_out;
    int e = in_sizes[6];
    int L = in_sizes[2] / (64 * 64);

    // 0) layer-0 embeddings + histogram w/ rank recording
    int GB = (e + 255) / 256;
    k_init_hist<<<GA + GB, 256>>>((const float4*)ue, (const float4*)ie,
                                  (float4*)out, rows, e);
    // 1) rowptr scan (counts self-zeroed)
    k_scan<<<1, 1024>>>(N_NODES);
    // 2) atomic-free scatter
    k_scatter<<<(e + 255) / 256, 256>>>(rows, cols, vals, e);

    // 3-5) fused layers — 592 blocks = 4/SM on 148 SMs = one wave
    const int DG = 592;
    const int rpb = (N_NODES + DG - 1) / DG;             // 254
    for (int k = 0; k < L; ++k)
        k_layer<<<DG, 256>>>(W1, b1, W2, b2, out, k, rpb, (k + 1 < L) ? 1 : 0);
}